// round 16
// baseline (speedup 1.0000x reference)
#include <cuda_runtime.h>
#include <cuda_fp16.h>
#include <cstdint>
#include <cstddef>

// Problem constants
#define NTOT 12000
#define TT   6000
#define HH   4000
#define DD   256
#define NH   8
#define HD   32
#define EV   64
#define LOG2E 1.4426950408889634f
#define NSPLIT 4

typedef unsigned long long u64;
typedef unsigned int u32;
typedef unsigned short u16;
typedef unsigned char u8;

// Scratch (device globals -- no allocation allowed)
__device__ __half g_Qx[(size_t)NTOT * DD];   // fp16 query
__device__ __half g_Kx[(size_t)NTOT * DD];   // fp16 key
__device__ __half g_Vx[(size_t)NTOT * DD];   // fp16 value
__device__ __half g_Wh[4 * DD * DD];         // fp16 Wq,Wk,Wv,Wo
__device__ __half g_Qh[(size_t)TT * DD];     // projected+scaled queries (log2 domain)
__device__ __half g_Kh[(size_t)HH * DD];     // projected keys
__device__ __half g_Vh[(size_t)HH * DD];     // projected values
__device__ __half g_Vtt[(size_t)HH * DD];    // tiled V^T: [s/32][dim][s%32]
__device__ u8     g_code[(size_t)TT * HH];   // packed mask/edge codes (0x80 = masked)
__device__ float  g_Op[NSPLIT][(size_t)TT * DD];  // unnormalized partial O
__device__ float  g_lp[NSPLIT][NH][TT];           // partial softmax denominators
__device__ __half g_Ah[(size_t)NTOT * DD];   // assembled attn_all (fp16)

// ---------- helpers ----------
__device__ __forceinline__ float ex2f(float x) {
    float r; asm("ex2.approx.ftz.f32 %0, %1;" : "=f"(r) : "f"(x)); return r;
}
__device__ __forceinline__ u32 packh2(float lo, float hi) {
    u32 r; asm("cvt.rn.f16x2.f32 %0, %1, %2;" : "=r"(r) : "f"(hi), "f"(lo)); return r;
}
__device__ __forceinline__ u32 smem_u32(const void* p) {
    u32 a; asm("{ .reg .u64 t; cvta.to.shared.u64 t, %1; cvt.u32.u64 %0, t; }" : "=r"(a) : "l"(p));
    return a;
}
__device__ __forceinline__ void cp16(void* dst, const void* src) {
    asm volatile("cp.async.cg.shared.global [%0], [%1], 16;"
                 :: "r"(smem_u32(dst)), "l"(src) : "memory");
}
#define CP_COMMIT() asm volatile("cp.async.commit_group;" ::: "memory")
#define CP_WAIT1()  asm volatile("cp.async.wait_group 1;" ::: "memory")
#define CP_WAIT0()  asm volatile("cp.async.wait_group 0;" ::: "memory")

// mma.sync m16n8k16 f16 x f16 -> f32
__device__ __forceinline__ void mma_f16(float* d, const u32* a, u32 b0, u32 b1) {
    asm volatile(
        "mma.sync.aligned.m16n8k16.row.col.f32.f16.f16.f32 "
        "{%0,%1,%2,%3}, {%4,%5,%6,%7}, {%8,%9}, {%0,%1,%2,%3};"
        : "+f"(d[0]), "+f"(d[1]), "+f"(d[2]), "+f"(d[3])
        : "r"(a[0]), "r"(a[1]), "r"(a[2]), "r"(a[3]), "r"(b0), "r"(b1));
}

// ---------------------------------------------------------------------------
// Fused prep: fp16 converts (x, W), code packing, g_Ah zeroing.
// ---------------------------------------------------------------------------
__global__ void __launch_bounds__(256) prep_kernel(
    const float* __restrict__ q, const float* __restrict__ k,
    const float* __restrict__ v,
    const float* __restrict__ wq, const float* __restrict__ wk,
    const float* __restrict__ wv, const float* __restrict__ wo,
    const int* __restrict__ adj, const int* __restrict__ cidx)
{
    const int y = blockIdx.y;
    const int i = blockIdx.x * 256 + threadIdx.x;

    if (y < 3) {
        if (i < NTOT * DD / 4) {
            const float* src = (y == 0) ? q : (y == 1) ? k : v;
            __half* dst = (y == 0) ? g_Qx : (y == 1) ? g_Kx : g_Vx;
            float4 f = ((const float4*)src)[i];
            uint2 o; o.x = packh2(f.x, f.y); o.y = packh2(f.z, f.w);
            ((uint2*)dst)[i] = o;
        }
    } else if (y < 7) {
        if (i < DD * DD / 4) {
            int wsel = y - 3;
            const float* src = (wsel == 0) ? wq : (wsel == 1) ? wk
                             : (wsel == 2) ? wv : wo;
            __half* dst = g_Wh + (size_t)wsel * DD * DD;
            float4 f = ((const float4*)src)[i];
            uint2 o; o.x = packh2(f.x, f.y); o.y = packh2(f.z, f.w);
            ((uint2*)dst)[i] = o;
        }
    } else if (y == 7) {
        if (i < TT * HH / 32) {
            const int4* ap = (const int4*)adj  + (size_t)i * 8;
            const int4* cp = (const int4*)cidx + (size_t)i * 8;
            u32 ob[8];
#pragma unroll
            for (int j = 0; j < 8; j++) {
                int4 a = ap[j]; int4 c = cp[j];
                u32 b0 = a.x ? ((u32)c.x & 63u) : 0x80u;
                u32 b1 = a.y ? ((u32)c.y & 63u) : 0x80u;
                u32 b2 = a.z ? ((u32)c.z & 63u) : 0x80u;
                u32 b3 = a.w ? ((u32)c.w & 63u) : 0x80u;
                ob[j] = b0 | (b1 << 8) | (b2 << 16) | (b3 << 24);
            }
            uint4* dst = (uint4*)(g_code + (size_t)i * 32);
            dst[0] = make_uint4(ob[0], ob[1], ob[2], ob[3]);
            dst[1] = make_uint4(ob[4], ob[5], ob[6], ob[7]);
        }
    } else {
        if (i < NTOT * DD * 2 / 16)
            ((uint4*)g_Ah)[i] = make_uint4(0u, 0u, 0u, 0u);
    }
}

// ---------------------------------------------------------------------------
// fp16 mma GEMM: Y[m,:] = (X[src(m),:] @ W^T + bias) * scale
// ---------------------------------------------------------------------------
__global__ void __launch_bounds__(256, 3) gemm_h_kernel(
    const __half* __restrict__ Xh, const int* __restrict__ idx,
    const __half* __restrict__ Wh, const float* __restrict__ bias,
    float* __restrict__ Yf, __half* __restrict__ Yh, int M, float scale)
{
    __shared__ __align__(16) __half Ah[2][128][40];
    __shared__ __align__(16) __half Bh[2][64][40];

    const int tid = threadIdx.x;
    const int w = tid >> 5, lane = tid & 31;
    const int g = lane >> 2, tq = lane & 3;
    const int wm = (w & 3) * 32, wn = (w >> 2) * 32;
    const int m0 = blockIdx.y * 128, n0 = blockIdx.x * 64;

    const int ar = tid >> 2, aseg = tid & 3;
    int xr0 = m0 + ar;       if (xr0 >= M) xr0 = M - 1;
    int xr1 = m0 + ar + 64;  if (xr1 >= M) xr1 = M - 1;
    if (idx) { xr0 = idx[xr0]; xr1 = idx[xr1]; }
    const __half* xp0 = Xh + (size_t)xr0 * DD + aseg * 8;
    const __half* xp1 = Xh + (size_t)xr1 * DD + aseg * 8;
    const __half* wp  = Wh + (size_t)(n0 + ar) * DD + aseg * 8;

    float C[2][4][4];
#pragma unroll
    for (int mt = 0; mt < 2; mt++)
#pragma unroll
        for (int nt = 0; nt < 4; nt++)
#pragma unroll
            for (int j = 0; j < 4; j++) C[mt][nt][j] = 0.f;

    cp16(&Ah[0][ar][aseg * 8],      xp0);
    cp16(&Ah[0][ar + 64][aseg * 8], xp1);
    if (ar < 64) cp16(&Bh[0][ar][aseg * 8], wp);
    CP_COMMIT();

    for (int kc = 0; kc < 8; kc++) {
        const int buf = kc & 1;
        if (kc + 1 < 8) {
            int ko = (kc + 1) * 32;
            cp16(&Ah[buf ^ 1][ar][aseg * 8],      xp0 + ko);
            cp16(&Ah[buf ^ 1][ar + 64][aseg * 8], xp1 + ko);
            if (ar < 64) cp16(&Bh[buf ^ 1][ar][aseg * 8], wp + ko);
            CP_COMMIT();
            CP_WAIT1();
        } else {
            CP_WAIT0();
        }
        __syncthreads();

#pragma unroll
        for (int kt = 0; kt < 2; kt++) {
            u32 A[2][4];
#pragma unroll
            for (int mt = 0; mt < 2; mt++) {
                const __half* ap = &Ah[buf][wm + mt * 16 + g][kt * 16 + 2 * tq];
                A[mt][0] = *(const u32*)ap;
                A[mt][1] = *(const u32*)(ap + 8 * 40);
                A[mt][2] = *(const u32*)(ap + 8);
                A[mt][3] = *(const u32*)(ap + 8 * 40 + 8);
            }
#pragma unroll
            for (int nt = 0; nt < 4; nt++) {
                const __half* bp = &Bh[buf][wn + nt * 8 + g][kt * 16 + 2 * tq];
                u32 b0 = *(const u32*)bp;
                u32 b1 = *(const u32*)(bp + 8);
                mma_f16(C[0][nt], A[0], b0, b1);
                mma_f16(C[1][nt], A[1], b0, b1);
            }
        }
        __syncthreads();
    }

#pragma unroll
    for (int nt = 0; nt < 4; nt++) {
        int n = n0 + wn + nt * 8 + 2 * tq;
        float b0 = bias[n], b1 = bias[n + 1];
#pragma unroll
        for (int mt = 0; mt < 2; mt++) {
            int mA = m0 + wm + mt * 16 + g;
            int mB = mA + 8;
            float v0 = (C[mt][nt][0] + b0) * scale;
            float v1 = (C[mt][nt][1] + b1) * scale;
            float v2 = (C[mt][nt][2] + b0) * scale;
            float v3 = (C[mt][nt][3] + b1) * scale;
            if (Yh) {
                if (mA < M) *(u32*)(Yh + (size_t)mA * DD + n) = packh2(v0, v1);
                if (mB < M) *(u32*)(Yh + (size_t)mB * DD + n) = packh2(v2, v3);
            } else {
                if (mA < M) { float2 t = {v0, v1}; *(float2*)(Yf + (size_t)mA * DD + n) = t; }
                if (mB < M) { float2 t = {v2, v3}; *(float2*)(Yf + (size_t)mB * DD + n) = t; }
            }
        }
    }
}

// ---------------------------------------------------------------------------
// V transpose to tiled layout: g_Vh[4000][256] -> g_Vtt[s/32][dim][s%32]
// ---------------------------------------------------------------------------
__global__ void __launch_bounds__(256) transpose_v_kernel()
{
    __shared__ __half t[32][34];
    int s0 = blockIdx.x * 32, d0 = blockIdx.y * 32;
    int x = threadIdx.x & 31, y = threadIdx.x >> 5;
#pragma unroll
    for (int i = 0; i < 32; i += 8)
        t[y + i][x] = g_Vh[(size_t)(s0 + y + i) * DD + d0 + x];
    __syncthreads();
#pragma unroll
    for (int i = 0; i < 32; i += 8) {
        int s = s0 + x, d = d0 + y + i;
        g_Vtt[(size_t)(s >> 5) * (DD * 32) + d * 32 + (s & 31)] = t[x][y + i];
    }
}

// ---------------------------------------------------------------------------
__global__ void copy_head_kernel(const int* __restrict__ ghead)
{
    int i = blockIdx.x * 256 + threadIdx.x;
    if (i < HH * 32) {
        int row = i >> 5, c4 = i & 31;
        int r = ghead[row];
        ((uint4*)(g_Ah + (size_t)r * DD))[c4] = ((const uint4*)(g_Qx + (size_t)r * DD))[c4];
    }
}

// ---------------------------------------------------------------------------
// Combine split-K partials and normalize: g_Ah[gtail[t]][d] = sum O / sum l
// ---------------------------------------------------------------------------
__global__ void __launch_bounds__(256) attn_combine_kernel(const int* __restrict__ gtail)
{
    int i = blockIdx.x * 256 + threadIdx.x;   // over TT*DD/4 float4-groups
    if (i >= TT * DD / 4) return;
    int t = i >> 6;                // tail
    int d4 = (i & 63) * 4;         // dim base
    int h = d4 >> 5;               // head
    float lsum = 0.f;
    float4 osum = make_float4(0.f, 0.f, 0.f, 0.f);
#pragma unroll
    for (int s = 0; s < NSPLIT; s++) {
        lsum += g_lp[s][h][t];
        float4 o = ((const float4*)(g_Op[s] + (size_t)t * DD + d4))[0];
        osum.x += o.x; osum.y += o.y; osum.z += o.z; osum.w += o.w;
    }
    float inv = 1.0f / lsum;
    uint2 o;
    o.x = packh2(osum.x * inv, osum.y * inv);
    o.y = packh2(osum.z * inv, osum.w * inv);
    *(uint2*)(g_Ah + (size_t)gtail[t] * DD + d4) = o;
}

// ---------------------------------------------------------------------------
// mma.sync fp16 flash attention: 32 tails x 8 heads per block, 32-key stages,
// split-K over keys (grid.y = NSPLIT). Multiplicative softmax:
//   p = exp2(S) * etab[head][code_byte],  etab[*][>=64] = 0 (incl. 0x80 mask)
// -> ex2 decoupled from the table gather (off the critical path), no selects.
// ---------------------------------------------------------------------------
#define NST (HH / 32)

struct AttnSmem {
    __half Ks [2][32][264];   // [buf][key][256 dims + 8 pad]   528B rows
    __half Vts[2][256][40];   // [buf][dim][32 keys + 8 pad]    80B rows
    u8     codeS[2][32][48];  // [buf][tail][32 codes + 16 pad] 48B rows
    float  etab[NH][256];     // e^bias per head, indexed by raw code byte
};
#define ATTN_SMEM_BYTES ((int)sizeof(AttnSmem))

__device__ __forceinline__ void stage32(AttnSmem* s, int b, int it, int tid, int t0)
{
    const int s0 = it * 32;
#pragma unroll
    for (int i = 0; i < 4; i++) {       // K: 32 rows x 512B = 1024 cp16
        int e = tid + i * 256;
        int r = e >> 5, seg = e & 31;
        cp16(&s->Ks[b][r][seg * 8], g_Kh + ((size_t)(s0 + r) * DD + seg * 8));
    }
#pragma unroll
    for (int i = 0; i < 4; i++) {       // Vt: contiguous 16KB
        int e = tid + i * 256;
        int d = e >> 2, seg = e & 3;
        cp16(&s->Vts[b][d][seg * 8], g_Vtt + ((size_t)it * (DD * 32) + d * 32 + seg * 8));
    }
    if (tid < 64) {                     // codes: 32 rows x 32B
        int r = tid >> 1, seg = tid & 1;
        int tr = t0 + r; if (tr > TT - 1) tr = TT - 1;
        cp16(&s->codeS[b][r][seg * 16], g_code + (size_t)tr * HH + s0 + seg * 16);
    }
}

__global__ void __launch_bounds__(256, 2) attn_mma_kernel(const float* __restrict__ edge_emb)
{
    extern __shared__ char smraw[];
    AttnSmem* sm = (AttnSmem*)smraw;

    const int tid = threadIdx.x;
    const int w   = tid >> 5;          // warp = head
    const int lane = tid & 31;
    const int g   = lane >> 2;
    const int tq  = lane & 3;
    const int t0  = blockIdx.x * 32;
    const int ky  = blockIdx.y;        // key split
    const int s_beg = (ky * NST) / NSPLIT;
    const int s_end = ((ky + 1) * NST) / NSPLIT;

    // etab[h][c]: c < 64 -> e^bias = exp2(bias * log2e); else (incl. 0x80) -> 0
    for (int i = tid; i < NH * 256; i += 256) {
        int hh = i >> 8, c = i & 255;
        sm->etab[hh][c] = (c < EV) ? ex2f(edge_emb[c * NH + hh] * LOG2E) : 0.f;
    }

    // Q A-fragments, 2 m-tiles (rows clamped for last block)
    u32 Qa[2][2][4];
#pragma unroll
    for (int m = 0; m < 2; m++) {
        int r0 = t0 + m * 16 + g;      if (r0 > TT - 1) r0 = TT - 1;
        int r1 = t0 + m * 16 + g + 8;  if (r1 > TT - 1) r1 = TT - 1;
#pragma unroll
        for (int kt = 0; kt < 2; kt++) {
            const __half* q0 = g_Qh + (size_t)r0 * DD + w * HD + kt * 16 + 2 * tq;
            const __half* q1 = g_Qh + (size_t)r1 * DD + w * HD + kt * 16 + 2 * tq;
            Qa[m][kt][0] = *(const u32*)q0;
            Qa[m][kt][1] = *(const u32*)q1;
            Qa[m][kt][2] = *(const u32*)(q0 + 8);
            Qa[m][kt][3] = *(const u32*)(q1 + 8);
        }
    }

    float O[2][4][4];
#pragma unroll
    for (int m = 0; m < 2; m++)
#pragma unroll
        for (int n = 0; n < 4; n++)
#pragma unroll
            for (int j = 0; j < 4; j++) O[m][n][j] = 0.f;
    float l[2][2] = {{0.f, 0.f}, {0.f, 0.f}};

    stage32(sm, 0, s_beg, tid, t0);
    CP_COMMIT();

    for (int it = s_beg; it < s_end; it++) {
        const int buf = (it - s_beg) & 1;
        if (it + 1 < s_end) {
            stage32(sm, buf ^ 1, it + 1, tid, t0);
            CP_COMMIT();
            CP_WAIT1();
        } else {
            CP_WAIT0();
        }
        __syncthreads();

        // ---- QK + multiplicative softmax ----
        u32 Pa[2][8];
#pragma unroll
        for (int m = 0; m < 2; m++) {
#pragma unroll
            for (int nt = 0; nt < 4; nt++) {
                float S4[4] = {0.f, 0.f, 0.f, 0.f};
#pragma unroll
                for (int kt = 0; kt < 2; kt++) {
                    const __half* kp = &sm->Ks[buf][nt * 8 + g][w * HD + kt * 16 + 2 * tq];
                    u32 b0 = *(const u32*)kp;
                    u32 b1 = *(const u32*)(kp + 8);
                    mma_f16(S4, Qa[m][kt], b0, b1);
                }
                u32 wA = *(const u16*)&sm->codeS[buf][m * 16 + g][nt * 8 + 2 * tq];
                u32 wB = *(const u16*)&sm->codeS[buf][m * 16 + g + 8][nt * 8 + 2 * tq];
                const float* et = sm->etab[w];
                // ex2 issues immediately (independent of table gather)
                float e0 = ex2f(S4[0]), e1 = ex2f(S4[1]);
                float e2 = ex2f(S4[2]), e3 = ex2f(S4[3]);
                float p00 = e0 * et[wA & 0xFFu];
                float p01 = e1 * et[wA >> 8];
                float p10 = e2 * et[wB & 0xFFu];
                float p11 = e3 * et[wB >> 8];
                l[m][0] += p00 + p01;
                l[m][1] += p10 + p11;
                Pa[m][nt * 2 + 0] = packh2(p00, p01);
                Pa[m][nt * 2 + 1] = packh2(p10, p11);
            }
        }

        // ---- PV: O[m][nd] += P[m] . V  (2 k16 frags over 32 keys) ----
#pragma unroll
        for (int nd = 0; nd < 4; nd++) {
#pragma unroll
            for (int kf = 0; kf < 2; kf++) {
                const __half* vp = &sm->Vts[buf][w * HD + nd * 8 + g][kf * 16 + 2 * tq];
                u32 b0 = *(const u32*)vp;
                u32 b1 = *(const u32*)(vp + 8);
                mma_f16(O[0][nd], &Pa[0][kf * 4], b0, b1);
                mma_f16(O[1][nd], &Pa[1][kf * 4], b0, b1);
            }
        }
        __syncthreads();
    }

    // quad-reduce l; write unnormalized partials (guarded for last block)
#pragma unroll
    for (int m = 0; m < 2; m++) {
        float lm0 = l[m][0], lm1 = l[m][1];
        lm0 += __shfl_xor_sync(0xffffffffu, lm0, 1);
        lm0 += __shfl_xor_sync(0xffffffffu, lm0, 2);
        lm1 += __shfl_xor_sync(0xffffffffu, lm1, 1);
        lm1 += __shfl_xor_sync(0xffffffffu, lm1, 2);

        int tg0 = t0 + m * 16 + g;
        int tg1 = tg0 + 8;
        if (tg0 < TT) {
            if (tq == 0) g_lp[ky][w][tg0] = lm0;
            float* d0 = g_Op[ky] + (size_t)tg0 * DD + w * HD;
#pragma unroll
            for (int nd = 0; nd < 4; nd++) {
                float2 v = {O[m][nd][0], O[m][nd][1]};
                *(float2*)(d0 + nd * 8 + 2 * tq) = v;
            }
        }
        if (tg1 < TT) {
            if (tq == 0) g_lp[ky][w][tg1] = lm1;
            float* d1 = g_Op[ky] + (size_t)tg1 * DD + w * HD;
#pragma unroll
            for (int nd = 0; nd < 4; nd++) {
                float2 v = {O[m][nd][2], O[m][nd][3]};
                *(float2*)(d1 + nd * 8 + 2 * tq) = v;
            }
        }
    }
}

// ---------------------------------------------------------------------------
extern "C" void kernel_launch(void* const* d_in, const int* in_sizes, int n_in,
                              void* d_out, int out_size)
{
    const float* query = (const float*)d_in[0];
    const float* key   = (const float*)d_in[1];
    const float* value = (const float*)d_in[2];
    const int*   adj   = (const int*)d_in[3];
    const int*   cidx  = (const int*)d_in[4];
    const int*   gtail = (const int*)d_in[5];
    const int*   ghead = (const int*)d_in[6];
    const float* Wq = (const float*)d_in[7];
    const float* bq = (const float*)d_in[8];
    const float* Wk = (const float*)d_in[9];
    const float* bk = (const float*)d_in[10];
    const float* Wv = (const float*)d_in[11];
    const float* bv = (const float*)d_in[12];
    const float* Wo = (const float*)d_in[13];
    const float* bo = (const float*)d_in[14];
    const float* edge = (const float*)d_in[15];
    float* out = (float*)d_out;

    __half *pQx, *pKx, *pVx, *pWh, *pQh, *pKh, *pVh, *pAh;
    cudaGetSymbolAddress((void**)&pQx, g_Qx);
    cudaGetSymbolAddress((void**)&pKx, g_Kx);
    cudaGetSymbolAddress((void**)&pVx, g_Vx);
    cudaGetSymbolAddress((void**)&pWh, g_Wh);
    cudaGetSymbolAddress((void**)&pQh, g_Qh);
    cudaGetSymbolAddress((void**)&pKh, g_Kh);
    cudaGetSymbolAddress((void**)&pVh, g_Vh);
    cudaGetSymbolAddress((void**)&pAh, g_Ah);

    cudaFuncSetAttribute(attn_mma_kernel,
                         cudaFuncAttributeMaxDynamicSharedMemorySize, ATTN_SMEM_BYTES);

    const float SCALE_Q = 0.17677669529663687f * LOG2E;  // 32^-0.5 * log2(e)

    // 1: fused prep (converts + code pack + zero)
    prep_kernel<<<dim3(3000, 9), 256>>>(query, key, value, Wq, Wk, Wv, Wo, adj, cidx);

    // 2-4: projections (fp16 mma)
    gemm_h_kernel<<<dim3(4, (TT + 127) / 128), 256>>>(
        pQx, gtail, pWh + 0 * DD * DD, bq, nullptr, pQh, TT, SCALE_Q);
    gemm_h_kernel<<<dim3(4, (HH + 127) / 128), 256>>>(
        pKx, ghead, pWh + 1 * DD * DD, bk, nullptr, pKh, HH, 1.0f);
    gemm_h_kernel<<<dim3(4, (HH + 127) / 128), 256>>>(
        pVx, ghead, pWh + 2 * DD * DD, bv, nullptr, pVh, HH, 1.0f);

    // 5: V transpose to tiled layout
    transpose_v_kernel<<<dim3(HH / 32, DD / 32), 256>>>();

    // 6: attention (split-K over keys, 4 ways)
    attn_mma_kernel<<<dim3((TT + 31) / 32, NSPLIT), 256, ATTN_SMEM_BYTES>>>(edge);

    // 7: combine + normalize partials into g_Ah
    attn_combine_kernel<<<(TT * DD / 4 + 255) / 256, 256>>>(gtail);

    // 8: head-row copy
    copy_head_kernel<<<(HH * 32 + 255) / 256, 256>>>(ghead);

    // 9: output projection (f32 out)
    gemm_h_kernel<<<dim3(4, (NTOT + 127) / 128), 256>>>(
        pAh, nullptr, pWh + 3 * DD * DD, bo, out, nullptr, NTOT, 1.0f);
}

// round 17
// speedup vs baseline: 1.1009x; 1.1009x over previous
#include <cuda_runtime.h>
#include <cuda_fp16.h>
#include <cstdint>
#include <cstddef>

// Problem constants
#define NTOT 12000
#define TT   6000
#define HH   4000
#define DD   256
#define NH   8
#define HD   32
#define EV   64
#define LOG2E 1.4426950408889634f
#define NSPLIT 4

typedef unsigned long long u64;
typedef unsigned int u32;
typedef unsigned short u16;
typedef unsigned char u8;

// Scratch (device globals -- no allocation allowed)
__device__ __half g_Qx[(size_t)NTOT * DD];   // fp16 query
__device__ __half g_Kx[(size_t)NTOT * DD];   // fp16 key
__device__ __half g_Vx[(size_t)NTOT * DD];   // fp16 value
__device__ __half g_Wh[4 * DD * DD];         // fp16 Wq,Wk,Wv,Wo
__device__ __half g_Qh[(size_t)TT * DD];     // projected+scaled queries (log2 domain)
__device__ __half g_Kh[(size_t)HH * DD];     // projected keys
__device__ __half g_Vh[(size_t)HH * DD];     // projected values
__device__ __half g_Vtt[(size_t)HH * DD];    // tiled V^T: [s/32][dim][s%32]
__device__ u8     g_code[(size_t)TT * HH];   // packed mask/edge codes (0x80 = masked)
__device__ float  g_Op[NSPLIT][(size_t)TT * DD];  // unnormalized partial O
__device__ float  g_lp[NSPLIT][NH][TT];           // partial softmax denominators
__device__ __half g_Ah[(size_t)NTOT * DD];   // assembled attn_all (fp16)

// ---------- helpers ----------
__device__ __forceinline__ float ex2f(float x) {
    float r; asm("ex2.approx.ftz.f32 %0, %1;" : "=f"(r) : "f"(x)); return r;
}
__device__ __forceinline__ u32 packh2(float lo, float hi) {
    u32 r; asm("cvt.rn.f16x2.f32 %0, %1, %2;" : "=r"(r) : "f"(hi), "f"(lo)); return r;
}
__device__ __forceinline__ u32 smem_u32(const void* p) {
    u32 a; asm("{ .reg .u64 t; cvta.to.shared.u64 t, %1; cvt.u32.u64 %0, t; }" : "=r"(a) : "l"(p));
    return a;
}
__device__ __forceinline__ void cp16(void* dst, const void* src) {
    asm volatile("cp.async.cg.shared.global [%0], [%1], 16;"
                 :: "r"(smem_u32(dst)), "l"(src) : "memory");
}
#define CP_COMMIT() asm volatile("cp.async.commit_group;" ::: "memory")
#define CP_WAIT1()  asm volatile("cp.async.wait_group 1;" ::: "memory")
#define CP_WAIT0()  asm volatile("cp.async.wait_group 0;" ::: "memory")

// mma.sync m16n8k16 f16 x f16 -> f32
__device__ __forceinline__ void mma_f16(float* d, const u32* a, u32 b0, u32 b1) {
    asm volatile(
        "mma.sync.aligned.m16n8k16.row.col.f32.f16.f16.f32 "
        "{%0,%1,%2,%3}, {%4,%5,%6,%7}, {%8,%9}, {%0,%1,%2,%3};"
        : "+f"(d[0]), "+f"(d[1]), "+f"(d[2]), "+f"(d[3])
        : "r"(a[0]), "r"(a[1]), "r"(a[2]), "r"(a[3]), "r"(b0), "r"(b1));
}

// ---------------------------------------------------------------------------
// Fused prep: fp16 converts (x, W), code packing, g_Ah zeroing.
// ---------------------------------------------------------------------------
__global__ void __launch_bounds__(256) prep_kernel(
    const float* __restrict__ q, const float* __restrict__ k,
    const float* __restrict__ v,
    const float* __restrict__ wq, const float* __restrict__ wk,
    const float* __restrict__ wv, const float* __restrict__ wo,
    const int* __restrict__ adj, const int* __restrict__ cidx)
{
    const int y = blockIdx.y;
    const int i = blockIdx.x * 256 + threadIdx.x;

    if (y < 3) {
        if (i < NTOT * DD / 4) {
            const float* src = (y == 0) ? q : (y == 1) ? k : v;
            __half* dst = (y == 0) ? g_Qx : (y == 1) ? g_Kx : g_Vx;
            float4 f = ((const float4*)src)[i];
            uint2 o; o.x = packh2(f.x, f.y); o.y = packh2(f.z, f.w);
            ((uint2*)dst)[i] = o;
        }
    } else if (y < 7) {
        if (i < DD * DD / 4) {
            int wsel = y - 3;
            const float* src = (wsel == 0) ? wq : (wsel == 1) ? wk
                             : (wsel == 2) ? wv : wo;
            __half* dst = g_Wh + (size_t)wsel * DD * DD;
            float4 f = ((const float4*)src)[i];
            uint2 o; o.x = packh2(f.x, f.y); o.y = packh2(f.z, f.w);
            ((uint2*)dst)[i] = o;
        }
    } else if (y == 7) {
        if (i < TT * HH / 32) {
            const int4* ap = (const int4*)adj  + (size_t)i * 8;
            const int4* cp = (const int4*)cidx + (size_t)i * 8;
            u32 ob[8];
#pragma unroll
            for (int j = 0; j < 8; j++) {
                int4 a = ap[j]; int4 c = cp[j];
                u32 b0 = a.x ? ((u32)c.x & 63u) : 0x80u;
                u32 b1 = a.y ? ((u32)c.y & 63u) : 0x80u;
                u32 b2 = a.z ? ((u32)c.z & 63u) : 0x80u;
                u32 b3 = a.w ? ((u32)c.w & 63u) : 0x80u;
                ob[j] = b0 | (b1 << 8) | (b2 << 16) | (b3 << 24);
            }
            uint4* dst = (uint4*)(g_code + (size_t)i * 32);
            dst[0] = make_uint4(ob[0], ob[1], ob[2], ob[3]);
            dst[1] = make_uint4(ob[4], ob[5], ob[6], ob[7]);
        }
    } else {
        if (i < NTOT * DD * 2 / 16)
            ((uint4*)g_Ah)[i] = make_uint4(0u, 0u, 0u, 0u);
    }
}

// ---------------------------------------------------------------------------
// fp16 mma GEMM: Y[m,:] = (X[src(m),:] @ W^T + bias) * scale
// ---------------------------------------------------------------------------
__global__ void __launch_bounds__(256, 3) gemm_h_kernel(
    const __half* __restrict__ Xh, const int* __restrict__ idx,
    const __half* __restrict__ Wh, const float* __restrict__ bias,
    float* __restrict__ Yf, __half* __restrict__ Yh, int M, float scale)
{
    __shared__ __align__(16) __half Ah[2][128][40];
    __shared__ __align__(16) __half Bh[2][64][40];

    const int tid = threadIdx.x;
    const int w = tid >> 5, lane = tid & 31;
    const int g = lane >> 2, tq = lane & 3;
    const int wm = (w & 3) * 32, wn = (w >> 2) * 32;
    const int m0 = blockIdx.y * 128, n0 = blockIdx.x * 64;

    const int ar = tid >> 2, aseg = tid & 3;
    int xr0 = m0 + ar;       if (xr0 >= M) xr0 = M - 1;
    int xr1 = m0 + ar + 64;  if (xr1 >= M) xr1 = M - 1;
    if (idx) { xr0 = idx[xr0]; xr1 = idx[xr1]; }
    const __half* xp0 = Xh + (size_t)xr0 * DD + aseg * 8;
    const __half* xp1 = Xh + (size_t)xr1 * DD + aseg * 8;
    const __half* wp  = Wh + (size_t)(n0 + ar) * DD + aseg * 8;

    float C[2][4][4];
#pragma unroll
    for (int mt = 0; mt < 2; mt++)
#pragma unroll
        for (int nt = 0; nt < 4; nt++)
#pragma unroll
            for (int j = 0; j < 4; j++) C[mt][nt][j] = 0.f;

    cp16(&Ah[0][ar][aseg * 8],      xp0);
    cp16(&Ah[0][ar + 64][aseg * 8], xp1);
    if (ar < 64) cp16(&Bh[0][ar][aseg * 8], wp);
    CP_COMMIT();

    for (int kc = 0; kc < 8; kc++) {
        const int buf = kc & 1;
        if (kc + 1 < 8) {
            int ko = (kc + 1) * 32;
            cp16(&Ah[buf ^ 1][ar][aseg * 8],      xp0 + ko);
            cp16(&Ah[buf ^ 1][ar + 64][aseg * 8], xp1 + ko);
            if (ar < 64) cp16(&Bh[buf ^ 1][ar][aseg * 8], wp + ko);
            CP_COMMIT();
            CP_WAIT1();
        } else {
            CP_WAIT0();
        }
        __syncthreads();

#pragma unroll
        for (int kt = 0; kt < 2; kt++) {
            u32 A[2][4];
#pragma unroll
            for (int mt = 0; mt < 2; mt++) {
                const __half* ap = &Ah[buf][wm + mt * 16 + g][kt * 16 + 2 * tq];
                A[mt][0] = *(const u32*)ap;
                A[mt][1] = *(const u32*)(ap + 8 * 40);
                A[mt][2] = *(const u32*)(ap + 8);
                A[mt][3] = *(const u32*)(ap + 8 * 40 + 8);
            }
#pragma unroll
            for (int nt = 0; nt < 4; nt++) {
                const __half* bp = &Bh[buf][wn + nt * 8 + g][kt * 16 + 2 * tq];
                u32 b0 = *(const u32*)bp;
                u32 b1 = *(const u32*)(bp + 8);
                mma_f16(C[0][nt], A[0], b0, b1);
                mma_f16(C[1][nt], A[1], b0, b1);
            }
        }
        __syncthreads();
    }

#pragma unroll
    for (int nt = 0; nt < 4; nt++) {
        int n = n0 + wn + nt * 8 + 2 * tq;
        float b0 = bias[n], b1 = bias[n + 1];
#pragma unroll
        for (int mt = 0; mt < 2; mt++) {
            int mA = m0 + wm + mt * 16 + g;
            int mB = mA + 8;
            float v0 = (C[mt][nt][0] + b0) * scale;
            float v1 = (C[mt][nt][1] + b1) * scale;
            float v2 = (C[mt][nt][2] + b0) * scale;
            float v3 = (C[mt][nt][3] + b1) * scale;
            if (Yh) {
                if (mA < M) *(u32*)(Yh + (size_t)mA * DD + n) = packh2(v0, v1);
                if (mB < M) *(u32*)(Yh + (size_t)mB * DD + n) = packh2(v2, v3);
            } else {
                if (mA < M) { float2 t = {v0, v1}; *(float2*)(Yf + (size_t)mA * DD + n) = t; }
                if (mB < M) { float2 t = {v2, v3}; *(float2*)(Yf + (size_t)mB * DD + n) = t; }
            }
        }
    }
}

// ---------------------------------------------------------------------------
// V transpose to tiled layout: g_Vh[4000][256] -> g_Vtt[s/32][dim][s%32]
// ---------------------------------------------------------------------------
__global__ void __launch_bounds__(256) transpose_v_kernel()
{
    __shared__ __half t[32][34];
    int s0 = blockIdx.x * 32, d0 = blockIdx.y * 32;
    int x = threadIdx.x & 31, y = threadIdx.x >> 5;
#pragma unroll
    for (int i = 0; i < 32; i += 8)
        t[y + i][x] = g_Vh[(size_t)(s0 + y + i) * DD + d0 + x];
    __syncthreads();
#pragma unroll
    for (int i = 0; i < 32; i += 8) {
        int s = s0 + x, d = d0 + y + i;
        g_Vtt[(size_t)(s >> 5) * (DD * 32) + d * 32 + (s & 31)] = t[x][y + i];
    }
}

// ---------------------------------------------------------------------------
__global__ void copy_head_kernel(const int* __restrict__ ghead)
{
    int i = blockIdx.x * 256 + threadIdx.x;
    if (i < HH * 32) {
        int row = i >> 5, c4 = i & 31;
        int r = ghead[row];
        ((uint4*)(g_Ah + (size_t)r * DD))[c4] = ((const uint4*)(g_Qx + (size_t)r * DD))[c4];
    }
}

// ---------------------------------------------------------------------------
// Combine split-K partials and normalize: g_Ah[gtail[t]][d] = sum O / sum l
// ---------------------------------------------------------------------------
__global__ void __launch_bounds__(256) attn_combine_kernel(const int* __restrict__ gtail)
{
    int i = blockIdx.x * 256 + threadIdx.x;   // over TT*DD/4 float4-groups
    if (i >= TT * DD / 4) return;
    int t = i >> 6;                // tail
    int d4 = (i & 63) * 4;         // dim base
    int h = d4 >> 5;               // head
    float lsum = 0.f;
    float4 osum = make_float4(0.f, 0.f, 0.f, 0.f);
#pragma unroll
    for (int s = 0; s < NSPLIT; s++) {
        lsum += g_lp[s][h][t];
        float4 o = ((const float4*)(g_Op[s] + (size_t)t * DD + d4))[0];
        osum.x += o.x; osum.y += o.y; osum.z += o.z; osum.w += o.w;
    }
    float inv = 1.0f / lsum;
    uint2 o;
    o.x = packh2(osum.x * inv, osum.y * inv);
    o.y = packh2(osum.z * inv, osum.w * inv);
    *(uint2*)(g_Ah + (size_t)gtail[t] * DD + d4) = o;
}

// ---------------------------------------------------------------------------
// mma.sync fp16 flash attention: 64 tails x 8 heads per block (512 threads,
// 2 warps per head covering 32-tail halves), 32-key stages, split-K (grid.y).
// K/Vt tiles staged ONCE per 64 tails -> staging L2 stream halved.
// Multiplicative softmax: p = exp2(S) * etab[head][code_byte].
// ---------------------------------------------------------------------------
#define NST (HH / 32)

struct AttnSmem {
    __half Ks [2][32][264];   // [buf][key][256 dims + 8 pad]   528B rows
    __half Vts[2][256][40];   // [buf][dim][32 keys + 8 pad]    80B rows
    u8     codeS[2][64][48];  // [buf][tail(64)][32 codes+pad]  48B rows
    float  etab[NH][256];     // e^bias per head, indexed by raw code byte
};
#define ATTN_SMEM_BYTES ((int)sizeof(AttnSmem))

__device__ __forceinline__ void stage32(AttnSmem* s, int b, int it, int tid, int t0)
{
    const int s0 = it * 32;
#pragma unroll
    for (int i = 0; i < 2; i++) {       // K: 1024 cp16 over 512 threads
        int e = tid + i * 512;
        int r = e >> 5, seg = e & 31;
        cp16(&s->Ks[b][r][seg * 8], g_Kh + ((size_t)(s0 + r) * DD + seg * 8));
    }
#pragma unroll
    for (int i = 0; i < 2; i++) {       // Vt: contiguous 16KB, 1024 cp16
        int e = tid + i * 512;
        int d = e >> 2, seg = e & 3;
        cp16(&s->Vts[b][d][seg * 8], g_Vtt + ((size_t)it * (DD * 32) + d * 32 + seg * 8));
    }
    if (tid < 128) {                    // codes: 64 rows x 32B = 128 cp16
        int r = tid >> 1, seg = tid & 1;
        int tr = t0 + r; if (tr > TT - 1) tr = TT - 1;
        cp16(&s->codeS[b][r][seg * 16], g_code + (size_t)tr * HH + s0 + seg * 16);
    }
}

__global__ void __launch_bounds__(512, 1) attn_mma_kernel(const float* __restrict__ edge_emb)
{
    extern __shared__ char smraw[];
    AttnSmem* sm = (AttnSmem*)smraw;

    const int tid = threadIdx.x;
    const int w16 = tid >> 5;          // warp 0..15
    const int hh  = w16 >> 1;          // head 0..7
    const int toff = (w16 & 1) * 32;   // tail half within the 64-tail block
    const int lane = tid & 31;
    const int g   = lane >> 2;
    const int tq  = lane & 3;
    const int t0  = blockIdx.x * 64;
    const int ky  = blockIdx.y;        // key split
    const int s_beg = (ky * NST) / NSPLIT;
    const int s_end = ((ky + 1) * NST) / NSPLIT;

    // etab[h][c]: c < 64 -> e^bias; else (incl. 0x80 mask) -> 0
    for (int i = tid; i < NH * 256; i += 512) {
        int h8 = i >> 8, c = i & 255;
        sm->etab[h8][c] = (c < EV) ? ex2f(edge_emb[c * NH + h8] * LOG2E) : 0.f;
    }

    // Q A-fragments, 2 m-tiles (rows clamped for last block)
    u32 Qa[2][2][4];
#pragma unroll
    for (int m = 0; m < 2; m++) {
        int r0 = t0 + toff + m * 16 + g;      if (r0 > TT - 1) r0 = TT - 1;
        int r1 = t0 + toff + m * 16 + g + 8;  if (r1 > TT - 1) r1 = TT - 1;
#pragma unroll
        for (int kt = 0; kt < 2; kt++) {
            const __half* q0 = g_Qh + (size_t)r0 * DD + hh * HD + kt * 16 + 2 * tq;
            const __half* q1 = g_Qh + (size_t)r1 * DD + hh * HD + kt * 16 + 2 * tq;
            Qa[m][kt][0] = *(const u32*)q0;
            Qa[m][kt][1] = *(const u32*)q1;
            Qa[m][kt][2] = *(const u32*)(q0 + 8);
            Qa[m][kt][3] = *(const u32*)(q1 + 8);
        }
    }

    float O[2][4][4];
#pragma unroll
    for (int m = 0; m < 2; m++)
#pragma unroll
        for (int n = 0; n < 4; n++)
#pragma unroll
            for (int j = 0; j < 4; j++) O[m][n][j] = 0.f;
    float l[2][2] = {{0.f, 0.f}, {0.f, 0.f}};

    stage32(sm, 0, s_beg, tid, t0);
    CP_COMMIT();

    for (int it = s_beg; it < s_end; it++) {
        const int buf = (it - s_beg) & 1;
        if (it + 1 < s_end) {
            stage32(sm, buf ^ 1, it + 1, tid, t0);
            CP_COMMIT();
            CP_WAIT1();
        } else {
            CP_WAIT0();
        }
        __syncthreads();

        // ---- QK + multiplicative softmax ----
        u32 Pa[2][8];
#pragma unroll
        for (int m = 0; m < 2; m++) {
#pragma unroll
            for (int nt = 0; nt < 4; nt++) {
                float S4[4] = {0.f, 0.f, 0.f, 0.f};
#pragma unroll
                for (int kt = 0; kt < 2; kt++) {
                    const __half* kp = &sm->Ks[buf][nt * 8 + g][hh * HD + kt * 16 + 2 * tq];
                    u32 b0 = *(const u32*)kp;
                    u32 b1 = *(const u32*)(kp + 8);
                    mma_f16(S4, Qa[m][kt], b0, b1);
                }
                u32 wA = *(const u16*)&sm->codeS[buf][toff + m * 16 + g][nt * 8 + 2 * tq];
                u32 wB = *(const u16*)&sm->codeS[buf][toff + m * 16 + g + 8][nt * 8 + 2 * tq];
                const float* et = sm->etab[hh];
                float e0 = ex2f(S4[0]), e1 = ex2f(S4[1]);
                float e2 = ex2f(S4[2]), e3 = ex2f(S4[3]);
                float p00 = e0 * et[wA & 0xFFu];
                float p01 = e1 * et[wA >> 8];
                float p10 = e2 * et[wB & 0xFFu];
                float p11 = e3 * et[wB >> 8];
                l[m][0] += p00 + p01;
                l[m][1] += p10 + p11;
                Pa[m][nt * 2 + 0] = packh2(p00, p01);
                Pa[m][nt * 2 + 1] = packh2(p10, p11);
            }
        }

        // ---- PV: O[m][nd] += P[m] . V  (2 k16 frags over 32 keys) ----
#pragma unroll
        for (int nd = 0; nd < 4; nd++) {
#pragma unroll
            for (int kf = 0; kf < 2; kf++) {
                const __half* vp = &sm->Vts[buf][hh * HD + nd * 8 + g][kf * 16 + 2 * tq];
                u32 b0 = *(const u32*)vp;
                u32 b1 = *(const u32*)(vp + 8);
                mma_f16(O[0][nd], &Pa[0][kf * 4], b0, b1);
                mma_f16(O[1][nd], &Pa[1][kf * 4], b0, b1);
            }
        }
        __syncthreads();
    }

    // quad-reduce l; write unnormalized partials (guarded for last block)
#pragma unroll
    for (int m = 0; m < 2; m++) {
        float lm0 = l[m][0], lm1 = l[m][1];
        lm0 += __shfl_xor_sync(0xffffffffu, lm0, 1);
        lm0 += __shfl_xor_sync(0xffffffffu, lm0, 2);
        lm1 += __shfl_xor_sync(0xffffffffu, lm1, 1);
        lm1 += __shfl_xor_sync(0xffffffffu, lm1, 2);

        int tg0 = t0 + toff + m * 16 + g;
        int tg1 = tg0 + 8;
        if (tg0 < TT) {
            if (tq == 0) g_lp[ky][hh][tg0] = lm0;
            float* d0 = g_Op[ky] + (size_t)tg0 * DD + hh * HD;
#pragma unroll
            for (int nd = 0; nd < 4; nd++) {
                float2 v = {O[m][nd][0], O[m][nd][1]};
                *(float2*)(d0 + nd * 8 + 2 * tq) = v;
            }
        }
        if (tg1 < TT) {
            if (tq == 0) g_lp[ky][hh][tg1] = lm1;
            float* d1 = g_Op[ky] + (size_t)tg1 * DD + hh * HD;
#pragma unroll
            for (int nd = 0; nd < 4; nd++) {
                float2 v = {O[m][nd][2], O[m][nd][3]};
                *(float2*)(d1 + nd * 8 + 2 * tq) = v;
            }
        }
    }
}

// ---------------------------------------------------------------------------
extern "C" void kernel_launch(void* const* d_in, const int* in_sizes, int n_in,
                              void* d_out, int out_size)
{
    const float* query = (const float*)d_in[0];
    const float* key   = (const float*)d_in[1];
    const float* value = (const float*)d_in[2];
    const int*   adj   = (const int*)d_in[3];
    const int*   cidx  = (const int*)d_in[4];
    const int*   gtail = (const int*)d_in[5];
    const int*   ghead = (const int*)d_in[6];
    const float* Wq = (const float*)d_in[7];
    const float* bq = (const float*)d_in[8];
    const float* Wk = (const float*)d_in[9];
    const float* bk = (const float*)d_in[10];
    const float* Wv = (const float*)d_in[11];
    const float* bv = (const float*)d_in[12];
    const float* Wo = (const float*)d_in[13];
    const float* bo = (const float*)d_in[14];
    const float* edge = (const float*)d_in[15];
    float* out = (float*)d_out;

    __half *pQx, *pKx, *pVx, *pWh, *pQh, *pKh, *pVh, *pAh;
    cudaGetSymbolAddress((void**)&pQx, g_Qx);
    cudaGetSymbolAddress((void**)&pKx, g_Kx);
    cudaGetSymbolAddress((void**)&pVx, g_Vx);
    cudaGetSymbolAddress((void**)&pWh, g_Wh);
    cudaGetSymbolAddress((void**)&pQh, g_Qh);
    cudaGetSymbolAddress((void**)&pKh, g_Kh);
    cudaGetSymbolAddress((void**)&pVh, g_Vh);
    cudaGetSymbolAddress((void**)&pAh, g_Ah);

    cudaFuncSetAttribute(attn_mma_kernel,
                         cudaFuncAttributeMaxDynamicSharedMemorySize, ATTN_SMEM_BYTES);

    const float SCALE_Q = 0.17677669529663687f * LOG2E;  // 32^-0.5 * log2(e)

    // 1: fused prep (converts + code pack + zero)
    prep_kernel<<<dim3(3000, 9), 256>>>(query, key, value, Wq, Wk, Wv, Wo, adj, cidx);

    // 2-4: projections (fp16 mma)
    gemm_h_kernel<<<dim3(4, (TT + 127) / 128), 256>>>(
        pQx, gtail, pWh + 0 * DD * DD, bq, nullptr, pQh, TT, SCALE_Q);
    gemm_h_kernel<<<dim3(4, (HH + 127) / 128), 256>>>(
        pKx, ghead, pWh + 1 * DD * DD, bk, nullptr, pKh, HH, 1.0f);
    gemm_h_kernel<<<dim3(4, (HH + 127) / 128), 256>>>(
        pVx, ghead, pWh + 2 * DD * DD, bv, nullptr, pVh, HH, 1.0f);

    // 5: V transpose to tiled layout
    transpose_v_kernel<<<dim3(HH / 32, DD / 32), 256>>>();

    // 6: attention (64 tails/block, split-K over keys)
    attn_mma_kernel<<<dim3((TT + 63) / 64, NSPLIT), 512, ATTN_SMEM_BYTES>>>(edge);

    // 7: combine + normalize partials into g_Ah
    attn_combine_kernel<<<(TT * DD / 4 + 255) / 256, 256>>>(gtail);

    // 8: head-row copy
    copy_head_kernel<<<(HH * 32 + 255) / 256, 256>>>(ghead);

    // 9: output projection (f32 out)
    gemm_h_kernel<<<dim3(4, (NTOT + 127) / 128), 256>>>(
        pAh, nullptr, pWh + 3 * DD * DD, bo, out, nullptr, NTOT, 1.0f);
}